// round 1
// baseline (speedup 1.0000x reference)
#include <cuda_runtime.h>
#include <cuda_bf16.h>
#include <math.h>

// Problem constants
#define S_LEN 2048
#define BATCH 2
#define HID   2048
#define NP    16
#define HN    128
#define M_ROWS (S_LEN*BATCH)     // 4096
#define QKV_N  (3*HID)           // 6144

// ---------------------------------------------------------------------------
// Scratch (device globals; no runtime allocation allowed)
// ---------------------------------------------------------------------------
__device__ float g_qkv[(size_t)M_ROWS * QKV_N];                 // [4096][6144]
__device__ float g_q[(size_t)BATCH * NP * S_LEN * HN];          // [b][n][s][d]
__device__ float g_k[(size_t)BATCH * NP * S_LEN * HN];
__device__ float g_v[(size_t)BATCH * NP * S_LEN * HN];
__device__ float g_ctx[(size_t)M_ROWS * HID];                   // [s][b][h]

// ---------------------------------------------------------------------------
// SGEMM (NT): C[M,N] = A[M,K] * W[N,K]^T + bias[N]
// BM=BN=128, BK=8, 256 threads, 8x8 micro-tile
// ---------------------------------------------------------------------------
#define GBM 128
#define GBN 128
#define GBK 8

__global__ __launch_bounds__(256) void sgemm_nt_bias(
    const float* __restrict__ A, const float* __restrict__ W,
    const float* __restrict__ bias, float* __restrict__ C,
    int M, int N, int K)
{
    __shared__ float As[GBK][GBM];
    __shared__ float Bs[GBK][GBN];

    const int tid = threadIdx.x;
    const int bx = blockIdx.x;   // N tile
    const int by = blockIdx.y;   // M tile
    const int tx = tid & 15;
    const int ty = tid >> 4;

    const int lrow = tid >> 1;         // 0..127
    const int lk   = (tid & 1) * 4;    // 0 or 4

    const float* Aptr = A + (size_t)(by*GBM + lrow)*K + lk;
    const float* Wptr = W + (size_t)(bx*GBN + lrow)*K + lk;

    float acc[8][8];
#pragma unroll
    for (int i = 0; i < 8; i++)
#pragma unroll
        for (int j = 0; j < 8; j++) acc[i][j] = 0.f;

    for (int k0 = 0; k0 < K; k0 += GBK) {
        float4 av = *(const float4*)(Aptr + k0);
        float4 bv = *(const float4*)(Wptr + k0);
        As[lk+0][lrow] = av.x; As[lk+1][lrow] = av.y;
        As[lk+2][lrow] = av.z; As[lk+3][lrow] = av.w;
        Bs[lk+0][lrow] = bv.x; Bs[lk+1][lrow] = bv.y;
        Bs[lk+2][lrow] = bv.z; Bs[lk+3][lrow] = bv.w;
        __syncthreads();

#pragma unroll
        for (int kk = 0; kk < GBK; kk++) {
            float a[8], b[8];
            *(float4*)&a[0] = *(const float4*)&As[kk][ty*8];
            *(float4*)&a[4] = *(const float4*)&As[kk][ty*8+4];
            *(float4*)&b[0] = *(const float4*)&Bs[kk][tx*8];
            *(float4*)&b[4] = *(const float4*)&Bs[kk][tx*8+4];
#pragma unroll
            for (int i = 0; i < 8; i++)
#pragma unroll
                for (int j = 0; j < 8; j++)
                    acc[i][j] += a[i] * b[j];
        }
        __syncthreads();
    }

    // epilogue
    float bvals[8];
#pragma unroll
    for (int j = 0; j < 8; j++) bvals[j] = bias[bx*GBN + tx*8 + j];

#pragma unroll
    for (int i = 0; i < 8; i++) {
        int row = by*GBM + ty*8 + i;
        float* cp = C + (size_t)row*N + bx*GBN + tx*8;
#pragma unroll
        for (int j = 0; j < 8; j += 4) {
            float4 v;
            v.x = acc[i][j+0] + bvals[j+0];
            v.y = acc[i][j+1] + bvals[j+1];
            v.z = acc[i][j+2] + bvals[j+2];
            v.w = acc[i][j+3] + bvals[j+3];
            *(float4*)(cp + j) = v;
        }
    }
}

// ---------------------------------------------------------------------------
// Rotary + QKV split/transpose: mixed[s][b][n][384] -> Q/K/V [b][n][s][128]
// One thread per (s,b,n,i) rotary pair (i in [0,64)).
// ---------------------------------------------------------------------------
__global__ __launch_bounds__(256) void rotary_split_kernel(
    const float* __restrict__ mixed,
    float* __restrict__ Q, float* __restrict__ K, float* __restrict__ V)
{
    int idx = blockIdx.x * blockDim.x + threadIdx.x;   // exact grid
    int i = idx & 63;
    int rest = idx >> 6;
    int n = rest & (NP - 1); rest >>= 4;
    int b = rest & (BATCH - 1);
    int s = rest >> 1;

    const float* src = mixed + (((size_t)(s*BATCH + b))*NP + n) * (3*HN);
    size_t dst = (((size_t)b*NP + n)*S_LEN + s) * HN;

    float expo = (float)(2*i) / (float)HN;
    float freq = powf(1e-4f, expo);
    float ang  = (float)s * freq;
    float sn, cs;
    sincosf(ang, &sn, &cs);

    float ql = src[i],       qr = src[i + 64];
    float kl = src[128 + i], kr = src[192 + i];

    Q[dst + i]      = cs*ql - sn*qr;
    Q[dst + 64 + i] = sn*ql + cs*qr;
    K[dst + i]      = cs*kl - sn*kr;
    K[dst + 64 + i] = sn*kl + cs*kr;
    V[dst + i]      = src[256 + i];
    V[dst + 64 + i] = src[320 + i];
}

// ---------------------------------------------------------------------------
// Causal flash attention, fp32.
// Grid: (S/128, NP, B). Block: 256 threads.
// BM=128 query rows, BN=64 key rows, D=128.
// Thread map: tr = tid>>3 (owns rows tr*4..tr*4+3), tc = tid&7
//   S phase : cols tc*8..tc*8+7  (4x8 accum)
//   PV phase: cols tc*16..tc*16+15 (4x16 accum)
// Output ctx[s][b][n*128 + d] (ready for dense GEMM)
// ---------------------------------------------------------------------------
#define FBM 128
#define FBN 64
#define QS_STRIDE 129
#define KS_STRIDE 129
#define PS_STRIDE 65

#define FA_SMEM_FLOATS (FBM*QS_STRIDE + FBN*KS_STRIDE + FBN*HN + FBM*PS_STRIDE)

__global__ __launch_bounds__(256, 1) void flash_attn_kernel(
    const float* __restrict__ Qg, const float* __restrict__ Kg,
    const float* __restrict__ Vg, float* __restrict__ ctx)
{
    extern __shared__ float sm[];
    float* Qs = sm;                               // [128][129]
    float* Ks = Qs + FBM*QS_STRIDE;               // [64][129]
    float* Vs = Ks + FBN*KS_STRIDE;               // [64][128]
    float* Ps = Vs + FBN*HN;                      // [128][65]

    const int qt = gridDim.x - 1 - blockIdx.x;    // heavy tiles first
    const int n  = blockIdx.y;
    const int b  = blockIdx.z;
    const int tid = threadIdx.x;
    const int tr = tid >> 3;   // 0..31
    const int tc = tid & 7;    // 0..7

    const size_t head = ((size_t)b*NP + n) * (size_t)S_LEN * HN;
    const int row0 = qt * FBM;
    const float qscale = 0.0883883476483184f;     // 1/sqrt(128)

    // Load Q tile (scaled)
    for (int idx = tid*4; idx < FBM*HN; idx += 256*4) {
        int r = idx >> 7, c = idx & 127;
        float4 v = *(const float4*)(Qg + head + (size_t)(row0 + r)*HN + c);
        float* q = &Qs[r*QS_STRIDE + c];
        q[0] = v.x*qscale; q[1] = v.y*qscale; q[2] = v.z*qscale; q[3] = v.w*qscale;
    }

    float m_i[4], l_i[4], O[4][16];
#pragma unroll
    for (int i = 0; i < 4; i++) {
        m_i[i] = -1e30f; l_i[i] = 0.f;
#pragma unroll
        for (int c = 0; c < 16; c++) O[i][c] = 0.f;
    }

    const int nkt = (row0 + FBM) / FBN;   // 2*(qt+1)
    for (int kt = 0; kt < nkt; kt++) {
        const int kr0 = kt * FBN;
        __syncthreads();   // Q ready (first iter) / prior PV reads done

        for (int idx = tid*4; idx < FBN*HN; idx += 256*4) {
            int r = idx >> 7, c = idx & 127;
            float4 kv = *(const float4*)(Kg + head + (size_t)(kr0 + r)*HN + c);
            float* kp = &Ks[r*KS_STRIDE + c];
            kp[0] = kv.x; kp[1] = kv.y; kp[2] = kv.z; kp[3] = kv.w;
            float4 vv = *(const float4*)(Vg + head + (size_t)(kr0 + r)*HN + c);
            *(float4*)&Vs[r*HN + c] = vv;
        }
        __syncthreads();

        // ---- S = Q K^T tile ----
        float acc[4][8];
#pragma unroll
        for (int i = 0; i < 4; i++)
#pragma unroll
            for (int j = 0; j < 8; j++) acc[i][j] = 0.f;

#pragma unroll 4
        for (int k = 0; k < HN; k++) {
            float a[4], bb[8];
#pragma unroll
            for (int i = 0; i < 4; i++) a[i] = Qs[(tr*4 + i)*QS_STRIDE + k];
#pragma unroll
            for (int j = 0; j < 8; j++) bb[j] = Ks[(tc*8 + j)*KS_STRIDE + k];
#pragma unroll
            for (int i = 0; i < 4; i++)
#pragma unroll
                for (int j = 0; j < 8; j++)
                    acc[i][j] += a[i] * bb[j];
        }

        // causal mask (only tiles crossing the diagonal)
        if (kr0 + FBN - 1 > row0) {
#pragma unroll
            for (int i = 0; i < 4; i++) {
                int rrow = row0 + tr*4 + i;
#pragma unroll
                for (int j = 0; j < 8; j++) {
                    int ccol = kr0 + tc*8 + j;
                    if (ccol > rrow) acc[i][j] = -1e30f;
                }
            }
        }

        // ---- online softmax ----
#pragma unroll
        for (int i = 0; i < 4; i++) {
            float mx = acc[i][0];
#pragma unroll
            for (int j = 1; j < 8; j++) mx = fmaxf(mx, acc[i][j]);
            mx = fmaxf(mx, __shfl_xor_sync(0xffffffffu, mx, 1));
            mx = fmaxf(mx, __shfl_xor_sync(0xffffffffu, mx, 2));
            mx = fmaxf(mx, __shfl_xor_sync(0xffffffffu, mx, 4));
            float mnew = fmaxf(m_i[i], mx);
            float corr = __expf(m_i[i] - mnew);
            float rsum = 0.f;
#pragma unroll
            for (int j = 0; j < 8; j++) {
                float p = __expf(acc[i][j] - mnew);
                Ps[(tr*4 + i)*PS_STRIDE + tc*8 + j] = p;
                rsum += p;
            }
            rsum += __shfl_xor_sync(0xffffffffu, rsum, 1);
            rsum += __shfl_xor_sync(0xffffffffu, rsum, 2);
            rsum += __shfl_xor_sync(0xffffffffu, rsum, 4);
            l_i[i] = l_i[i]*corr + rsum;
            m_i[i] = mnew;
#pragma unroll
            for (int c = 0; c < 16; c++) O[i][c] *= corr;
        }
        __syncthreads();   // Ps visible to all

        // ---- O += P @ V ----
#pragma unroll 4
        for (int key = 0; key < FBN; key++) {
            float p[4];
#pragma unroll
            for (int i = 0; i < 4; i++) p[i] = Ps[(tr*4 + i)*PS_STRIDE + key];
            const float* vrow = &Vs[key*HN + tc*16];
            float4 v0 = *(const float4*)(vrow);
            float4 v1 = *(const float4*)(vrow + 4);
            float4 v2 = *(const float4*)(vrow + 8);
            float4 v3 = *(const float4*)(vrow + 12);
#pragma unroll
            for (int i = 0; i < 4; i++) {
                O[i][0]  += p[i]*v0.x; O[i][1]  += p[i]*v0.y;
                O[i][2]  += p[i]*v0.z; O[i][3]  += p[i]*v0.w;
                O[i][4]  += p[i]*v1.x; O[i][5]  += p[i]*v1.y;
                O[i][6]  += p[i]*v1.z; O[i][7]  += p[i]*v1.w;
                O[i][8]  += p[i]*v2.x; O[i][9]  += p[i]*v2.y;
                O[i][10] += p[i]*v2.z; O[i][11] += p[i]*v2.w;
                O[i][12] += p[i]*v3.x; O[i][13] += p[i]*v3.y;
                O[i][14] += p[i]*v3.z; O[i][15] += p[i]*v3.w;
            }
        }
    }

    // ---- epilogue: normalize and write ctx[s][b][n*128+d] ----
#pragma unroll
    for (int i = 0; i < 4; i++) {
        int s = row0 + tr*4 + i;
        float inv = 1.0f / l_i[i];
        float* cp = ctx + ((size_t)s*BATCH + b)*HID + n*HN + tc*16;
#pragma unroll
        for (int c = 0; c < 16; c += 4) {
            float4 v;
            v.x = O[i][c+0]*inv; v.y = O[i][c+1]*inv;
            v.z = O[i][c+2]*inv; v.w = O[i][c+3]*inv;
            *(float4*)(cp + c) = v;
        }
    }
}

// ---------------------------------------------------------------------------
// Launch
// ---------------------------------------------------------------------------
extern "C" void kernel_launch(void* const* d_in, const int* in_sizes, int n_in,
                              void* d_out, int out_size)
{
    const float* hidden  = (const float*)d_in[0];
    // d_in[1] = attention_mask (causal; handled analytically)
    const float* w_qkv   = (const float*)d_in[2];
    const float* b_qkv   = (const float*)d_in[3];
    const float* w_dense = (const float*)d_in[4];
    const float* b_dense = (const float*)d_in[5];
    float* out = (float*)d_out;

    float *qkv, *q, *k, *v, *ctx;
    cudaGetSymbolAddress((void**)&qkv, g_qkv);
    cudaGetSymbolAddress((void**)&q,   g_q);
    cudaGetSymbolAddress((void**)&k,   g_k);
    cudaGetSymbolAddress((void**)&v,   g_v);
    cudaGetSymbolAddress((void**)&ctx, g_ctx);

    // 1) QKV projection: [4096,6144] = hidden[4096,2048] @ w_qkv[6144,2048]^T + b
    sgemm_nt_bias<<<dim3(QKV_N/GBN, M_ROWS/GBM), 256>>>(
        hidden, w_qkv, b_qkv, qkv, M_ROWS, QKV_N, HID);

    // 2) Rotary + split into [b][n][s][d]
    {
        int total = S_LEN * BATCH * NP * (HN/2);  // 4,194,304 threads
        rotary_split_kernel<<<total/256, 256>>>(qkv, q, k, v);
    }

    // 3) Causal flash attention -> ctx[s][b][h]
    {
        size_t smem = (size_t)FA_SMEM_FLOATS * sizeof(float);  // 165,120 B
        cudaFuncSetAttribute(flash_attn_kernel,
                             cudaFuncAttributeMaxDynamicSharedMemorySize, (int)smem);
        flash_attn_kernel<<<dim3(S_LEN/FBM, NP, BATCH), 256, smem>>>(q, k, v, ctx);
    }

    // 4) Dense projection: out[4096,2048] = ctx @ w_dense[2048,2048]^T + b
    sgemm_nt_bias<<<dim3(HID/GBN, M_ROWS/GBM), 256>>>(
        ctx, w_dense, b_dense, out, M_ROWS, HID, HID);
}

// round 2
// speedup vs baseline: 2.6247x; 2.6247x over previous
#include <cuda_runtime.h>
#include <cuda_bf16.h>
#include <math.h>
#include <stdint.h>

// Problem constants
#define S_LEN 2048
#define BATCH 2
#define HID   2048
#define NP    16
#define HN    128
#define M_ROWS (S_LEN*BATCH)     // 4096
#define QKV_N  (3*HID)           // 6144

// ---------------------------------------------------------------------------
// Scratch (device globals; no runtime allocation allowed)
// ---------------------------------------------------------------------------
__device__ float g_qkv[(size_t)M_ROWS * QKV_N];                 // [4096][6144]
__device__ float g_q[(size_t)BATCH * NP * S_LEN * HN];          // [b][n][s][d]
__device__ float g_k[(size_t)BATCH * NP * S_LEN * HN];
__device__ float g_v[(size_t)BATCH * NP * S_LEN * HN];
__device__ float g_ctx[(size_t)M_ROWS * HID];                   // [s][b][h]

// ---------------------------------------------------------------------------
// PTX helpers
// ---------------------------------------------------------------------------
__device__ __forceinline__ uint32_t smem_u32(const void* p) {
    return (uint32_t)__cvta_generic_to_shared(p);
}
__device__ __forceinline__ void ldsm_x4(uint32_t& r0, uint32_t& r1,
                                        uint32_t& r2, uint32_t& r3, uint32_t addr) {
    asm volatile("ldmatrix.sync.aligned.m8n8.x4.shared.b16 {%0,%1,%2,%3}, [%4];"
        : "=r"(r0), "=r"(r1), "=r"(r2), "=r"(r3) : "r"(addr));
}
__device__ __forceinline__ void mma_bf16(float* d, const uint32_t* a, const uint32_t* b) {
    asm volatile("mma.sync.aligned.m16n8k16.row.col.f32.bf16.bf16.f32 "
        "{%0,%1,%2,%3}, {%4,%5,%6,%7}, {%8,%9}, {%0,%1,%2,%3};"
        : "+f"(d[0]), "+f"(d[1]), "+f"(d[2]), "+f"(d[3])
        : "r"(a[0]), "r"(a[1]), "r"(a[2]), "r"(a[3]), "r"(b[0]), "r"(b[1]));
}

// ---------------------------------------------------------------------------
// HMMA bf16x3 GEMM (NT): C[M,N] = A[M,K] * W[N,K]^T + bias[N]
// fp32 inputs split on the fly: x = hi + lo (bf16 each);
// C = Ah*Bh + Ah*Bl + Al*Bh  (fp32 accumulate)  -> ~3e-5 relative error.
// BM=BN=128, BK=32, 256 threads (8 warps, 4x2), warp tile 32x64.
// Smem rows padded to 40 bf16 (80B) -> conflict-free ldmatrix.
// ---------------------------------------------------------------------------
#define TBM 128
#define TBN 128
#define TBK 32
#define TSTR 40
#define GEMM_SMEM_BYTES (2*2*TBM*TSTR*2*2)   // 2 stages * 2 prec * (A+B) = 81920

__global__ __launch_bounds__(256, 1) void hmma_gemm_nt_bias(
    const float* __restrict__ A, const float* __restrict__ W,
    const float* __restrict__ bias, float* __restrict__ C,
    int M, int N, int K)
{
    extern __shared__ __nv_bfloat16 smg[];
    __nv_bfloat16* As = smg;                       // [stage][prec][128][40]
    __nv_bfloat16* Bs = smg + 2*2*TBM*TSTR;

    const int tid  = threadIdx.x;
    const int bx   = blockIdx.x, by = blockIdx.y;
    const int warp = tid >> 5, lane = tid & 31;
    const int wr   = warp & 3;   // m-warp 0..3
    const int wc   = warp >> 2;  // n-warp 0..1

    // gmem load mapping: each thread loads 4 float4 per matrix per k-tile
    const int lr  = tid >> 3;           // row 0..31 (+32j)
    const int lkc = (tid & 7) * 4;      // k col 0..28

    const float* Ag = A + (size_t)(by * TBM) * K;
    const float* Wg = W + (size_t)(bx * TBN) * K;

    float4 sa[4], sb[4];

    auto load_g = [&](int kt) {
#pragma unroll
        for (int j = 0; j < 4; j++) {
            int r = lr + 32 * j;
            sa[j] = *(const float4*)(Ag + (size_t)r * K + kt * TBK + lkc);
            sb[j] = *(const float4*)(Wg + (size_t)r * K + kt * TBK + lkc);
        }
    };

    auto cvt_store = [&](int s) {
#pragma unroll
        for (int j = 0; j < 4; j++) {
            int r = lr + 32 * j;
#pragma unroll
            for (int mtx = 0; mtx < 2; mtx++) {
                float4 v = mtx ? sb[j] : sa[j];
                __nv_bfloat16* dst = mtx ? Bs : As;
                __nv_bfloat16 h0 = __float2bfloat16_rn(v.x);
                __nv_bfloat16 h1 = __float2bfloat16_rn(v.y);
                __nv_bfloat16 h2 = __float2bfloat16_rn(v.z);
                __nv_bfloat16 h3 = __float2bfloat16_rn(v.w);
                __nv_bfloat16 l0 = __float2bfloat16_rn(v.x - __bfloat162float(h0));
                __nv_bfloat16 l1 = __float2bfloat16_rn(v.y - __bfloat162float(h1));
                __nv_bfloat16 l2 = __float2bfloat16_rn(v.z - __bfloat162float(h2));
                __nv_bfloat16 l3 = __float2bfloat16_rn(v.w - __bfloat162float(h3));
                size_t bh = ((size_t)(s * 2 + 0) * TBM + r) * TSTR + lkc;
                size_t bl = ((size_t)(s * 2 + 1) * TBM + r) * TSTR + lkc;
                __nv_bfloat162 t;
                t.x = h0; t.y = h1; *(__nv_bfloat162*)&dst[bh]     = t;
                t.x = h2; t.y = h3; *(__nv_bfloat162*)&dst[bh + 2] = t;
                t.x = l0; t.y = l1; *(__nv_bfloat162*)&dst[bl]     = t;
                t.x = l2; t.y = l3; *(__nv_bfloat162*)&dst[bl + 2] = t;
            }
        }
    };

    float acc[2][8][4];
#pragma unroll
    for (int mi = 0; mi < 2; mi++)
#pragma unroll
        for (int ni = 0; ni < 8; ni++)
#pragma unroll
            for (int e = 0; e < 4; e++) acc[mi][ni][e] = 0.f;

    // ldmatrix lane addressing
    const int a_row = wr * 32 + (lane & 15);
    const int a_kh  = (lane >> 4) * 8;
    const int bg    = lane >> 3;
    const int b_row = wc * 64 + ((bg >> 1) << 3) + (lane & 7);
    const int b_kh  = (bg & 1) * 8;

    auto compute = [&](int s) {
#pragma unroll
        for (int kk = 0; kk < TBK; kk += 16) {
            uint32_t af[2][2][4];   // [prec][mi][4]
#pragma unroll
            for (int p = 0; p < 2; p++)
#pragma unroll
                for (int mi = 0; mi < 2; mi++) {
                    const __nv_bfloat16* ptr =
                        &As[((size_t)(s * 2 + p) * TBM + a_row + mi * 16) * TSTR + kk + a_kh];
                    ldsm_x4(af[p][mi][0], af[p][mi][1], af[p][mi][2], af[p][mi][3],
                            smem_u32(ptr));
                }
            uint32_t bf[2][8][2];   // [prec][ni][2]
#pragma unroll
            for (int p = 0; p < 2; p++)
#pragma unroll
                for (int np = 0; np < 4; np++) {
                    const __nv_bfloat16* ptr =
                        &Bs[((size_t)(s * 2 + p) * TBN + b_row + np * 16) * TSTR + kk + b_kh];
                    uint32_t r0, r1, r2, r3;
                    ldsm_x4(r0, r1, r2, r3, smem_u32(ptr));
                    bf[p][np * 2][0] = r0;     bf[p][np * 2][1] = r1;
                    bf[p][np * 2 + 1][0] = r2; bf[p][np * 2 + 1][1] = r3;
                }
#pragma unroll
            for (int mi = 0; mi < 2; mi++)
#pragma unroll
                for (int ni = 0; ni < 8; ni++) {
                    mma_bf16(acc[mi][ni], af[0][mi], bf[0][ni]);   // Ah*Bh
                    mma_bf16(acc[mi][ni], af[0][mi], bf[1][ni]);   // Ah*Bl
                    mma_bf16(acc[mi][ni], af[1][mi], bf[0][ni]);   // Al*Bh
                }
        }
    };

    const int ntiles = K / TBK;
    load_g(0);
    cvt_store(0);
    __syncthreads();
#pragma unroll 1
    for (int kt = 0; kt < ntiles; kt++) {
        if (kt + 1 < ntiles) load_g(kt + 1);
        compute(kt & 1);
        if (kt + 1 < ntiles) {
            cvt_store((kt + 1) & 1);
            __syncthreads();
        }
    }

    // epilogue
    const int gr = lane >> 2, gc = (lane & 3) * 2;
#pragma unroll
    for (int mi = 0; mi < 2; mi++) {
        int row = by * TBM + wr * 32 + mi * 16 + gr;
#pragma unroll
        for (int ni = 0; ni < 8; ni++) {
            int col = bx * TBN + wc * 64 + ni * 8 + gc;
            float b0 = bias[col], b1 = bias[col + 1];
            float2 v0, v1;
            v0.x = acc[mi][ni][0] + b0; v0.y = acc[mi][ni][1] + b1;
            v1.x = acc[mi][ni][2] + b0; v1.y = acc[mi][ni][3] + b1;
            *(float2*)&C[(size_t)row * N + col] = v0;
            *(float2*)&C[(size_t)(row + 8) * N + col] = v1;
        }
    }
}

// ---------------------------------------------------------------------------
// Rotary + QKV split/transpose: mixed[s][b][n][384] -> Q/K/V [b][n][s][128]
// ---------------------------------------------------------------------------
__global__ __launch_bounds__(256) void rotary_split_kernel(
    const float* __restrict__ mixed,
    float* __restrict__ Q, float* __restrict__ K, float* __restrict__ V)
{
    int idx = blockIdx.x * blockDim.x + threadIdx.x;
    int i = idx & 63;
    int rest = idx >> 6;
    int n = rest & (NP - 1); rest >>= 4;
    int b = rest & (BATCH - 1);
    int s = rest >> 1;

    const float* src = mixed + (((size_t)(s * BATCH + b)) * NP + n) * (3 * HN);
    size_t dst = (((size_t)b * NP + n) * S_LEN + s) * HN;

    float expo = (float)(2 * i) / (float)HN;
    float freq = powf(1e-4f, expo);
    float ang  = (float)s * freq;
    float sn, cs;
    sincosf(ang, &sn, &cs);

    float ql = src[i],       qr = src[i + 64];
    float kl = src[128 + i], kr = src[192 + i];

    Q[dst + i]      = cs * ql - sn * qr;
    Q[dst + 64 + i] = sn * ql + cs * qr;
    K[dst + i]      = cs * kl - sn * kr;
    K[dst + 64 + i] = sn * kl + cs * kr;
    V[dst + i]      = src[256 + i];
    V[dst + 64 + i] = src[320 + i];
}

// ---------------------------------------------------------------------------
// Causal flash attention, fp32 (unchanged from R1)
// ---------------------------------------------------------------------------
#define FBM 128
#define FBN 64
#define QS_STRIDE 129
#define KS_STRIDE 129
#define PS_STRIDE 65
#define FA_SMEM_FLOATS (FBM*QS_STRIDE + FBN*KS_STRIDE + FBN*HN + FBM*PS_STRIDE)

__global__ __launch_bounds__(256, 1) void flash_attn_kernel(
    const float* __restrict__ Qg, const float* __restrict__ Kg,
    const float* __restrict__ Vg, float* __restrict__ ctx)
{
    extern __shared__ float sm[];
    float* Qs = sm;
    float* Ks = Qs + FBM * QS_STRIDE;
    float* Vs = Ks + FBN * KS_STRIDE;
    float* Ps = Vs + FBN * HN;

    const int qt = gridDim.x - 1 - blockIdx.x;
    const int n  = blockIdx.y;
    const int b  = blockIdx.z;
    const int tid = threadIdx.x;
    const int tr = tid >> 3;
    const int tc = tid & 7;

    const size_t head = ((size_t)b * NP + n) * (size_t)S_LEN * HN;
    const int row0 = qt * FBM;
    const float qscale = 0.0883883476483184f;     // 1/sqrt(128)

    for (int idx = tid * 4; idx < FBM * HN; idx += 256 * 4) {
        int r = idx >> 7, c = idx & 127;
        float4 v = *(const float4*)(Qg + head + (size_t)(row0 + r) * HN + c);
        float* q = &Qs[r * QS_STRIDE + c];
        q[0] = v.x * qscale; q[1] = v.y * qscale; q[2] = v.z * qscale; q[3] = v.w * qscale;
    }

    float m_i[4], l_i[4], O[4][16];
#pragma unroll
    for (int i = 0; i < 4; i++) {
        m_i[i] = -1e30f; l_i[i] = 0.f;
#pragma unroll
        for (int c = 0; c < 16; c++) O[i][c] = 0.f;
    }

    const int nkt = (row0 + FBM) / FBN;
    for (int kt = 0; kt < nkt; kt++) {
        const int kr0 = kt * FBN;
        __syncthreads();

        for (int idx = tid * 4; idx < FBN * HN; idx += 256 * 4) {
            int r = idx >> 7, c = idx & 127;
            float4 kv = *(const float4*)(Kg + head + (size_t)(kr0 + r) * HN + c);
            float* kp = &Ks[r * KS_STRIDE + c];
            kp[0] = kv.x; kp[1] = kv.y; kp[2] = kv.z; kp[3] = kv.w;
            float4 vv = *(const float4*)(Vg + head + (size_t)(kr0 + r) * HN + c);
            *(float4*)&Vs[r * HN + c] = vv;
        }
        __syncthreads();

        float accf[4][8];
#pragma unroll
        for (int i = 0; i < 4; i++)
#pragma unroll
            for (int j = 0; j < 8; j++) accf[i][j] = 0.f;

#pragma unroll 4
        for (int k = 0; k < HN; k++) {
            float a[4], bb[8];
#pragma unroll
            for (int i = 0; i < 4; i++) a[i] = Qs[(tr * 4 + i) * QS_STRIDE + k];
#pragma unroll
            for (int j = 0; j < 8; j++) bb[j] = Ks[(tc * 8 + j) * KS_STRIDE + k];
#pragma unroll
            for (int i = 0; i < 4; i++)
#pragma unroll
                for (int j = 0; j < 8; j++)
                    accf[i][j] += a[i] * bb[j];
        }

        if (kr0 + FBN - 1 > row0) {
#pragma unroll
            for (int i = 0; i < 4; i++) {
                int rrow = row0 + tr * 4 + i;
#pragma unroll
                for (int j = 0; j < 8; j++) {
                    int ccol = kr0 + tc * 8 + j;
                    if (ccol > rrow) accf[i][j] = -1e30f;
                }
            }
        }

#pragma unroll
        for (int i = 0; i < 4; i++) {
            float mx = accf[i][0];
#pragma unroll
            for (int j = 1; j < 8; j++) mx = fmaxf(mx, accf[i][j]);
            mx = fmaxf(mx, __shfl_xor_sync(0xffffffffu, mx, 1));
            mx = fmaxf(mx, __shfl_xor_sync(0xffffffffu, mx, 2));
            mx = fmaxf(mx, __shfl_xor_sync(0xffffffffu, mx, 4));
            float mnew = fmaxf(m_i[i], mx);
            float corr = __expf(m_i[i] - mnew);
            float rsum = 0.f;
#pragma unroll
            for (int j = 0; j < 8; j++) {
                float p = __expf(accf[i][j] - mnew);
                Ps[(tr * 4 + i) * PS_STRIDE + tc * 8 + j] = p;
                rsum += p;
            }
            rsum += __shfl_xor_sync(0xffffffffu, rsum, 1);
            rsum += __shfl_xor_sync(0xffffffffu, rsum, 2);
            rsum += __shfl_xor_sync(0xffffffffu, rsum, 4);
            l_i[i] = l_i[i] * corr + rsum;
            m_i[i] = mnew;
#pragma unroll
            for (int c = 0; c < 16; c++) O[i][c] *= corr;
        }
        __syncthreads();

#pragma unroll 4
        for (int key = 0; key < FBN; key++) {
            float p[4];
#pragma unroll
            for (int i = 0; i < 4; i++) p[i] = Ps[(tr * 4 + i) * PS_STRIDE + key];
            const float* vrow = &Vs[key * HN + tc * 16];
            float4 v0 = *(const float4*)(vrow);
            float4 v1 = *(const float4*)(vrow + 4);
            float4 v2 = *(const float4*)(vrow + 8);
            float4 v3 = *(const float4*)(vrow + 12);
#pragma unroll
            for (int i = 0; i < 4; i++) {
                O[i][0]  += p[i] * v0.x; O[i][1]  += p[i] * v0.y;
                O[i][2]  += p[i] * v0.z; O[i][3]  += p[i] * v0.w;
                O[i][4]  += p[i] * v1.x; O[i][5]  += p[i] * v1.y;
                O[i][6]  += p[i] * v1.z; O[i][7]  += p[i] * v1.w;
                O[i][8]  += p[i] * v2.x; O[i][9]  += p[i] * v2.y;
                O[i][10] += p[i] * v2.z; O[i][11] += p[i] * v2.w;
                O[i][12] += p[i] * v3.x; O[i][13] += p[i] * v3.y;
                O[i][14] += p[i] * v3.z; O[i][15] += p[i] * v3.w;
            }
        }
    }

#pragma unroll
    for (int i = 0; i < 4; i++) {
        int s = row0 + tr * 4 + i;
        float inv = 1.0f / l_i[i];
        float* cp = ctx + ((size_t)s * BATCH + b) * HID + n * HN + tc * 16;
#pragma unroll
        for (int c = 0; c < 16; c += 4) {
            float4 v;
            v.x = O[i][c + 0] * inv; v.y = O[i][c + 1] * inv;
            v.z = O[i][c + 2] * inv; v.w = O[i][c + 3] * inv;
            *(float4*)(cp + c) = v;
        }
    }
}

// ---------------------------------------------------------------------------
// Launch
// ---------------------------------------------------------------------------
extern "C" void kernel_launch(void* const* d_in, const int* in_sizes, int n_in,
                              void* d_out, int out_size)
{
    const float* hidden  = (const float*)d_in[0];
    // d_in[1] = attention_mask (causal; handled analytically)
    const float* w_qkv   = (const float*)d_in[2];
    const float* b_qkv   = (const float*)d_in[3];
    const float* w_dense = (const float*)d_in[4];
    const float* b_dense = (const float*)d_in[5];
    float* out = (float*)d_out;

    float *qkv, *q, *k, *v, *ctx;
    cudaGetSymbolAddress((void**)&qkv, g_qkv);
    cudaGetSymbolAddress((void**)&q,   g_q);
    cudaGetSymbolAddress((void**)&k,   g_k);
    cudaGetSymbolAddress((void**)&v,   g_v);
    cudaGetSymbolAddress((void**)&ctx, g_ctx);

    static int attr_done = 0;
    if (!attr_done) {
        cudaFuncSetAttribute(hmma_gemm_nt_bias,
                             cudaFuncAttributeMaxDynamicSharedMemorySize, GEMM_SMEM_BYTES);
        cudaFuncSetAttribute(flash_attn_kernel,
                             cudaFuncAttributeMaxDynamicSharedMemorySize,
                             (int)(FA_SMEM_FLOATS * sizeof(float)));
        attr_done = 1;
    }

    // 1) QKV projection: [4096,6144] = hidden @ w_qkv^T + b   (tensor cores)
    hmma_gemm_nt_bias<<<dim3(QKV_N / TBN, M_ROWS / TBM), 256, GEMM_SMEM_BYTES>>>(
        hidden, w_qkv, b_qkv, qkv, M_ROWS, QKV_N, HID);

    // 2) Rotary + split into [b][n][s][d]
    {
        int total = S_LEN * BATCH * NP * (HN / 2);
        rotary_split_kernel<<<total / 256, 256>>>(qkv, q, k, v);
    }

    // 3) Causal flash attention -> ctx[s][b][h]
    {
        size_t smem = (size_t)FA_SMEM_FLOATS * sizeof(float);
        flash_attn_kernel<<<dim3(S_LEN / FBM, NP, BATCH), 256, smem>>>(q, k, v, ctx);
    }

    // 4) Dense projection: out[4096,2048] = ctx @ w_dense^T + b  (tensor cores)
    hmma_gemm_nt_bias<<<dim3(HID / TBN, M_ROWS / TBM), 256, GEMM_SMEM_BYTES>>>(
        ctx, w_dense, b_dense, out, M_ROWS, HID, HID);
}

// round 3
// speedup vs baseline: 3.4966x; 1.3322x over previous
#include <cuda_runtime.h>
#include <cuda_bf16.h>
#include <math.h>
#include <stdint.h>

// Problem constants
#define S_LEN 2048
#define BATCH 2
#define HID   2048
#define NP    16
#define HN    128
#define M_ROWS (S_LEN*BATCH)     // 4096
#define QKV_N  (3*HID)           // 6144

// ---------------------------------------------------------------------------
// Scratch (device globals; no runtime allocation allowed)
// ---------------------------------------------------------------------------
__device__ float g_qkv[(size_t)M_ROWS * QKV_N];                 // [4096][6144]
__device__ float g_q[(size_t)BATCH * NP * S_LEN * HN];          // [b][n][s][d]
__device__ float g_k[(size_t)BATCH * NP * S_LEN * HN];
__device__ float g_v[(size_t)BATCH * NP * S_LEN * HN];
__device__ float g_ctx[(size_t)M_ROWS * HID];                   // [s][b][h]

// ---------------------------------------------------------------------------
// PTX helpers
// ---------------------------------------------------------------------------
__device__ __forceinline__ uint32_t smem_u32(const void* p) {
    return (uint32_t)__cvta_generic_to_shared(p);
}
__device__ __forceinline__ void ldsm_x4(uint32_t& r0, uint32_t& r1,
                                        uint32_t& r2, uint32_t& r3, uint32_t addr) {
    asm volatile("ldmatrix.sync.aligned.m8n8.x4.shared.b16 {%0,%1,%2,%3}, [%4];"
        : "=r"(r0), "=r"(r1), "=r"(r2), "=r"(r3) : "r"(addr));
}
__device__ __forceinline__ void ldsm_x4_t(uint32_t& r0, uint32_t& r1,
                                          uint32_t& r2, uint32_t& r3, uint32_t addr) {
    asm volatile("ldmatrix.sync.aligned.m8n8.x4.trans.shared.b16 {%0,%1,%2,%3}, [%4];"
        : "=r"(r0), "=r"(r1), "=r"(r2), "=r"(r3) : "r"(addr));
}
__device__ __forceinline__ void mma_bf16(float* d, const uint32_t* a, const uint32_t* b) {
    asm volatile("mma.sync.aligned.m16n8k16.row.col.f32.bf16.bf16.f32 "
        "{%0,%1,%2,%3}, {%4,%5,%6,%7}, {%8,%9}, {%0,%1,%2,%3};"
        : "+f"(d[0]), "+f"(d[1]), "+f"(d[2]), "+f"(d[3])
        : "r"(a[0]), "r"(a[1]), "r"(a[2]), "r"(a[3]), "r"(b[0]), "r"(b[1]));
}
__device__ __forceinline__ uint32_t pack_bf2(float a, float b) {
    __nv_bfloat162 t;
    t.x = __float2bfloat16_rn(a);
    t.y = __float2bfloat16_rn(b);
    return *(uint32_t*)&t;
}

// ---------------------------------------------------------------------------
// HMMA bf16x3 GEMM (NT): C[M,N] = A[M,K] * W[N,K]^T + bias[N]   (unchanged R2)
// ---------------------------------------------------------------------------
#define TBM 128
#define TBN 128
#define TBK 32
#define TSTR 40
#define GEMM_SMEM_BYTES (2*2*TBM*TSTR*2*2)   // 81920

__global__ __launch_bounds__(256, 1) void hmma_gemm_nt_bias(
    const float* __restrict__ A, const float* __restrict__ W,
    const float* __restrict__ bias, float* __restrict__ C,
    int M, int N, int K)
{
    extern __shared__ __nv_bfloat16 smg[];
    __nv_bfloat16* As = smg;
    __nv_bfloat16* Bs = smg + 2*2*TBM*TSTR;

    const int tid  = threadIdx.x;
    const int bx   = blockIdx.x, by = blockIdx.y;
    const int warp = tid >> 5, lane = tid & 31;
    const int wr   = warp & 3;
    const int wc   = warp >> 2;

    const int lr  = tid >> 3;
    const int lkc = (tid & 7) * 4;

    const float* Ag = A + (size_t)(by * TBM) * K;
    const float* Wg = W + (size_t)(bx * TBN) * K;

    float4 sa[4], sb[4];

    auto load_g = [&](int kt) {
#pragma unroll
        for (int j = 0; j < 4; j++) {
            int r = lr + 32 * j;
            sa[j] = *(const float4*)(Ag + (size_t)r * K + kt * TBK + lkc);
            sb[j] = *(const float4*)(Wg + (size_t)r * K + kt * TBK + lkc);
        }
    };

    auto cvt_store = [&](int s) {
#pragma unroll
        for (int j = 0; j < 4; j++) {
            int r = lr + 32 * j;
#pragma unroll
            for (int mtx = 0; mtx < 2; mtx++) {
                float4 v = mtx ? sb[j] : sa[j];
                __nv_bfloat16* dst = mtx ? Bs : As;
                __nv_bfloat16 h0 = __float2bfloat16_rn(v.x);
                __nv_bfloat16 h1 = __float2bfloat16_rn(v.y);
                __nv_bfloat16 h2 = __float2bfloat16_rn(v.z);
                __nv_bfloat16 h3 = __float2bfloat16_rn(v.w);
                __nv_bfloat16 l0 = __float2bfloat16_rn(v.x - __bfloat162float(h0));
                __nv_bfloat16 l1 = __float2bfloat16_rn(v.y - __bfloat162float(h1));
                __nv_bfloat16 l2 = __float2bfloat16_rn(v.z - __bfloat162float(h2));
                __nv_bfloat16 l3 = __float2bfloat16_rn(v.w - __bfloat162float(h3));
                size_t bh = ((size_t)(s * 2 + 0) * TBM + r) * TSTR + lkc;
                size_t bl = ((size_t)(s * 2 + 1) * TBM + r) * TSTR + lkc;
                __nv_bfloat162 t;
                t.x = h0; t.y = h1; *(__nv_bfloat162*)&dst[bh]     = t;
                t.x = h2; t.y = h3; *(__nv_bfloat162*)&dst[bh + 2] = t;
                t.x = l0; t.y = l1; *(__nv_bfloat162*)&dst[bl]     = t;
                t.x = l2; t.y = l3; *(__nv_bfloat162*)&dst[bl + 2] = t;
            }
        }
    };

    float acc[2][8][4];
#pragma unroll
    for (int mi = 0; mi < 2; mi++)
#pragma unroll
        for (int ni = 0; ni < 8; ni++)
#pragma unroll
            for (int e = 0; e < 4; e++) acc[mi][ni][e] = 0.f;

    const int a_row = wr * 32 + (lane & 15);
    const int a_kh  = (lane >> 4) * 8;
    const int bg    = lane >> 3;
    const int b_row = wc * 64 + ((bg >> 1) << 3) + (lane & 7);
    const int b_kh  = (bg & 1) * 8;

    auto compute = [&](int s) {
#pragma unroll
        for (int kk = 0; kk < TBK; kk += 16) {
            uint32_t af[2][2][4];
#pragma unroll
            for (int p = 0; p < 2; p++)
#pragma unroll
                for (int mi = 0; mi < 2; mi++) {
                    const __nv_bfloat16* ptr =
                        &As[((size_t)(s * 2 + p) * TBM + a_row + mi * 16) * TSTR + kk + a_kh];
                    ldsm_x4(af[p][mi][0], af[p][mi][1], af[p][mi][2], af[p][mi][3],
                            smem_u32(ptr));
                }
            uint32_t bf[2][8][2];
#pragma unroll
            for (int p = 0; p < 2; p++)
#pragma unroll
                for (int np = 0; np < 4; np++) {
                    const __nv_bfloat16* ptr =
                        &Bs[((size_t)(s * 2 + p) * TBN + b_row + np * 16) * TSTR + kk + b_kh];
                    uint32_t r0, r1, r2, r3;
                    ldsm_x4(r0, r1, r2, r3, smem_u32(ptr));
                    bf[p][np * 2][0] = r0;     bf[p][np * 2][1] = r1;
                    bf[p][np * 2 + 1][0] = r2; bf[p][np * 2 + 1][1] = r3;
                }
#pragma unroll
            for (int mi = 0; mi < 2; mi++)
#pragma unroll
                for (int ni = 0; ni < 8; ni++) {
                    mma_bf16(acc[mi][ni], af[0][mi], bf[0][ni]);
                    mma_bf16(acc[mi][ni], af[0][mi], bf[1][ni]);
                    mma_bf16(acc[mi][ni], af[1][mi], bf[0][ni]);
                }
        }
    };

    const int ntiles = K / TBK;
    load_g(0);
    cvt_store(0);
    __syncthreads();
#pragma unroll 1
    for (int kt = 0; kt < ntiles; kt++) {
        if (kt + 1 < ntiles) load_g(kt + 1);
        compute(kt & 1);
        if (kt + 1 < ntiles) {
            cvt_store((kt + 1) & 1);
            __syncthreads();
        }
    }

    const int gr = lane >> 2, gc = (lane & 3) * 2;
#pragma unroll
    for (int mi = 0; mi < 2; mi++) {
        int row = by * TBM + wr * 32 + mi * 16 + gr;
#pragma unroll
        for (int ni = 0; ni < 8; ni++) {
            int col = bx * TBN + wc * 64 + ni * 8 + gc;
            float b0 = bias[col], b1 = bias[col + 1];
            float2 v0, v1;
            v0.x = acc[mi][ni][0] + b0; v0.y = acc[mi][ni][1] + b1;
            v1.x = acc[mi][ni][2] + b0; v1.y = acc[mi][ni][3] + b1;
            *(float2*)&C[(size_t)row * N + col] = v0;
            *(float2*)&C[(size_t)(row + 8) * N + col] = v1;
        }
    }
}

// ---------------------------------------------------------------------------
// Rotary + QKV split/transpose (unchanged)
// ---------------------------------------------------------------------------
__global__ __launch_bounds__(256) void rotary_split_kernel(
    const float* __restrict__ mixed,
    float* __restrict__ Q, float* __restrict__ K, float* __restrict__ V)
{
    int idx = blockIdx.x * blockDim.x + threadIdx.x;
    int i = idx & 63;
    int rest = idx >> 6;
    int n = rest & (NP - 1); rest >>= 4;
    int b = rest & (BATCH - 1);
    int s = rest >> 1;

    const float* src = mixed + (((size_t)(s * BATCH + b)) * NP + n) * (3 * HN);
    size_t dst = (((size_t)b * NP + n) * S_LEN + s) * HN;

    float expo = (float)(2 * i) / (float)HN;
    float freq = powf(1e-4f, expo);
    float ang  = (float)s * freq;
    float sn, cs;
    sincosf(ang, &sn, &cs);

    float ql = src[i],       qr = src[i + 64];
    float kl = src[128 + i], kr = src[192 + i];

    Q[dst + i]      = cs * ql - sn * qr;
    Q[dst + 64 + i] = sn * ql + cs * qr;
    K[dst + i]      = cs * kl - sn * kr;
    K[dst + 64 + i] = sn * kl + cs * kr;
    V[dst + i]      = src[256 + i];
    V[dst + 64 + i] = src[320 + i];
}

// ---------------------------------------------------------------------------
// HMMA flash attention (bf16x3, FA2-style).
// Grid (16, NP, B), 256 threads = 8 warps; warp w owns q rows [w*16, w*16+16).
// BM=128 q rows, BN=64 keys per tile, D=128.
// ---------------------------------------------------------------------------
#define FBM 128
#define FBN 64
#define FSTR 136
#define FA_SMEM_BYTES ((2*FBM*FSTR + 4*FBN*FSTR) * 2)   // 139264

__global__ __launch_bounds__(256, 1) void flash_hmma_kernel(
    const float* __restrict__ Qg, const float* __restrict__ Kg,
    const float* __restrict__ Vg, float* __restrict__ ctx)
{
    extern __shared__ __nv_bfloat16 fsm[];
    __nv_bfloat16* Qh = fsm;
    __nv_bfloat16* Ql = Qh + FBM * FSTR;
    __nv_bfloat16* Kh = Ql + FBM * FSTR;
    __nv_bfloat16* Kl = Kh + FBN * FSTR;
    __nv_bfloat16* Vh = Kl + FBN * FSTR;
    __nv_bfloat16* Vl = Vh + FBN * FSTR;

    const int qt = gridDim.x - 1 - blockIdx.x;    // heavy tiles first
    const int n  = blockIdx.y;
    const int b  = blockIdx.z;
    const int tid  = threadIdx.x;
    const int warp = tid >> 5, lane = tid & 31;

    const size_t head = ((size_t)b * NP + n) * (size_t)S_LEN * HN;
    const int row0 = qt * FBM;
    const float qscale = 0.0883883476483184f;     // 1/sqrt(128)

    // ---- load Q tile -> bf16 hi/lo smem (scaled) ----
#pragma unroll
    for (int j = 0; j < 16; j++) {
        int lin = tid + j * 256;               // 4096 float4s
        int r = lin >> 5, c = (lin & 31) * 4;
        float4 v = *(const float4*)(Qg + head + (size_t)(row0 + r) * HN + c);
        v.x *= qscale; v.y *= qscale; v.z *= qscale; v.w *= qscale;
        __nv_bfloat16 h0 = __float2bfloat16_rn(v.x);
        __nv_bfloat16 h1 = __float2bfloat16_rn(v.y);
        __nv_bfloat16 h2 = __float2bfloat16_rn(v.z);
        __nv_bfloat16 h3 = __float2bfloat16_rn(v.w);
        __nv_bfloat162 th0; th0.x = h0; th0.y = h1;
        __nv_bfloat162 th1; th1.x = h2; th1.y = h3;
        __nv_bfloat162 tl0;
        tl0.x = __float2bfloat16_rn(v.x - __bfloat162float(h0));
        tl0.y = __float2bfloat16_rn(v.y - __bfloat162float(h1));
        __nv_bfloat162 tl1;
        tl1.x = __float2bfloat16_rn(v.z - __bfloat162float(h2));
        tl1.y = __float2bfloat16_rn(v.w - __bfloat162float(h3));
        *(__nv_bfloat162*)&Qh[r * FSTR + c]     = th0;
        *(__nv_bfloat162*)&Qh[r * FSTR + c + 2] = th1;
        *(__nv_bfloat162*)&Ql[r * FSTR + c]     = tl0;
        *(__nv_bfloat162*)&Ql[r * FSTR + c + 2] = tl1;
    }

    // accumulators
    float oacc[16][4];
#pragma unroll
    for (int t = 0; t < 16; t++)
#pragma unroll
        for (int e = 0; e < 4; e++) oacc[t][e] = 0.f;
    float m_i[2] = {-1e30f, -1e30f};
    float l_i[2] = {0.f, 0.f};

    // fragment lane addressing
    const int a_row = warp * 16 + (lane & 15);
    const int a_kh  = (lane >> 4) * 8;
    const int b_r   = (lane >> 4) * 8 + (lane & 7);     // K (non-trans)
    const int b_kh  = ((lane >> 3) & 1) * 8;
    const int v_row = ((lane >> 3) & 1) * 8 + (lane & 7); // V (trans)
    const int v_col = (lane >> 4) * 8;
    const int gr    = lane >> 2;
    const int gc    = (lane & 3) * 2;
    const int wrow_last = row0 + warp * 16 + 15;

    const int nkt = (row0 + FBM) / FBN;
#pragma unroll 1
    for (int kt = 0; kt < nkt; kt++) {
        const int kr0 = kt * FBN;
        __syncthreads();   // prior compute done / Q ready

        // ---- load K,V tile -> bf16 hi/lo smem ----
#pragma unroll
        for (int j = 0; j < 8; j++) {
            int lin = tid + j * 256;            // 2048 float4s each
            int r = lin >> 5, c = (lin & 31) * 4;
            float4 kv = *(const float4*)(Kg + head + (size_t)(kr0 + r) * HN + c);
            float4 vv = *(const float4*)(Vg + head + (size_t)(kr0 + r) * HN + c);
            __nv_bfloat162 t;
            __nv_bfloat16 h;
            h = __float2bfloat16_rn(kv.x); t.x = h;
            Kl[r*FSTR+c  ] = __float2bfloat16_rn(kv.x - __bfloat162float(h));
            h = __float2bfloat16_rn(kv.y); t.y = h;
            Kl[r*FSTR+c+1] = __float2bfloat16_rn(kv.y - __bfloat162float(h));
            *(__nv_bfloat162*)&Kh[r*FSTR+c] = t;
            h = __float2bfloat16_rn(kv.z); t.x = h;
            Kl[r*FSTR+c+2] = __float2bfloat16_rn(kv.z - __bfloat162float(h));
            h = __float2bfloat16_rn(kv.w); t.y = h;
            Kl[r*FSTR+c+3] = __float2bfloat16_rn(kv.w - __bfloat162float(h));
            *(__nv_bfloat162*)&Kh[r*FSTR+c+2] = t;

            h = __float2bfloat16_rn(vv.x); t.x = h;
            Vl[r*FSTR+c  ] = __float2bfloat16_rn(vv.x - __bfloat162float(h));
            h = __float2bfloat16_rn(vv.y); t.y = h;
            Vl[r*FSTR+c+1] = __float2bfloat16_rn(vv.y - __bfloat162float(h));
            *(__nv_bfloat162*)&Vh[r*FSTR+c] = t;
            h = __float2bfloat16_rn(vv.z); t.x = h;
            Vl[r*FSTR+c+2] = __float2bfloat16_rn(vv.z - __bfloat162float(h));
            h = __float2bfloat16_rn(vv.w); t.y = h;
            Vl[r*FSTR+c+3] = __float2bfloat16_rn(vv.w - __bfloat162float(h));
            *(__nv_bfloat162*)&Vh[r*FSTR+c+2] = t;
        }
        __syncthreads();

        if (kr0 > wrow_last) continue;   // fully masked for this warp

        // ---- S = Q K^T (bf16x3) ----
        float sacc[8][4];
#pragma unroll
        for (int t = 0; t < 8; t++)
#pragma unroll
            for (int e = 0; e < 4; e++) sacc[t][e] = 0.f;

#pragma unroll
        for (int kk = 0; kk < 8; kk++) {
            uint32_t aH[4], aL[4];
            ldsm_x4(aH[0], aH[1], aH[2], aH[3],
                    smem_u32(&Qh[a_row * FSTR + kk * 16 + a_kh]));
            ldsm_x4(aL[0], aL[1], aL[2], aL[3],
                    smem_u32(&Ql[a_row * FSTR + kk * 16 + a_kh]));
#pragma unroll
            for (int nt2 = 0; nt2 < 4; nt2++) {
                uint32_t bh[4], bl[4];
                ldsm_x4(bh[0], bh[1], bh[2], bh[3],
                        smem_u32(&Kh[(nt2 * 16 + b_r) * FSTR + kk * 16 + b_kh]));
                ldsm_x4(bl[0], bl[1], bl[2], bl[3],
                        smem_u32(&Kl[(nt2 * 16 + b_r) * FSTR + kk * 16 + b_kh]));
                mma_bf16(sacc[nt2 * 2], aH, bh);
                mma_bf16(sacc[nt2 * 2], aH, bl);
                mma_bf16(sacc[nt2 * 2], aL, bh);
                mma_bf16(sacc[nt2 * 2 + 1], aH, bh + 2);
                mma_bf16(sacc[nt2 * 2 + 1], aH, bl + 2);
                mma_bf16(sacc[nt2 * 2 + 1], aL, bh + 2);
            }
        }

        // ---- causal mask ----
        if (kr0 + FBN - 1 > row0 + warp * 16) {
            int grow0 = row0 + warp * 16 + gr;
#pragma unroll
            for (int t = 0; t < 8; t++) {
                int colb = kr0 + t * 8 + gc;
                if (colb     > grow0)     sacc[t][0] = -1e30f;
                if (colb + 1 > grow0)     sacc[t][1] = -1e30f;
                if (colb     > grow0 + 8) sacc[t][2] = -1e30f;
                if (colb + 1 > grow0 + 8) sacc[t][3] = -1e30f;
            }
        }

        // ---- online softmax ----
        float mx0 = -1e30f, mx1 = -1e30f;
#pragma unroll
        for (int t = 0; t < 8; t++) {
            mx0 = fmaxf(mx0, fmaxf(sacc[t][0], sacc[t][1]));
            mx1 = fmaxf(mx1, fmaxf(sacc[t][2], sacc[t][3]));
        }
        mx0 = fmaxf(mx0, __shfl_xor_sync(0xffffffffu, mx0, 1));
        mx0 = fmaxf(mx0, __shfl_xor_sync(0xffffffffu, mx0, 2));
        mx1 = fmaxf(mx1, __shfl_xor_sync(0xffffffffu, mx1, 1));
        mx1 = fmaxf(mx1, __shfl_xor_sync(0xffffffffu, mx1, 2));
        float mn0 = fmaxf(m_i[0], mx0);
        float mn1 = fmaxf(m_i[1], mx1);
        float corr0 = __expf(m_i[0] - mn0);
        float corr1 = __expf(m_i[1] - mn1);

        uint32_t aPh[4][4], aPl[4][4];
        float rs0 = 0.f, rs1 = 0.f;
#pragma unroll
        for (int t = 0; t < 8; t++) {
            float p00 = __expf(sacc[t][0] - mn0);
            float p01 = __expf(sacc[t][1] - mn0);
            float p10 = __expf(sacc[t][2] - mn1);
            float p11 = __expf(sacc[t][3] - mn1);
            rs0 += p00 + p01;
            rs1 += p10 + p11;
            int kc = t >> 1, half = (t & 1) * 2;
            // hi
            float h00 = __bfloat162float(__float2bfloat16_rn(p00));
            float h01 = __bfloat162float(__float2bfloat16_rn(p01));
            float h10 = __bfloat162float(__float2bfloat16_rn(p10));
            float h11 = __bfloat162float(__float2bfloat16_rn(p11));
            aPh[kc][half]     = pack_bf2(h00, h01);
            aPh[kc][half + 1] = pack_bf2(h10, h11);
            aPl[kc][half]     = pack_bf2(p00 - h00, p01 - h01);
            aPl[kc][half + 1] = pack_bf2(p10 - h10, p11 - h11);
        }
        rs0 += __shfl_xor_sync(0xffffffffu, rs0, 1);
        rs0 += __shfl_xor_sync(0xffffffffu, rs0, 2);
        rs1 += __shfl_xor_sync(0xffffffffu, rs1, 1);
        rs1 += __shfl_xor_sync(0xffffffffu, rs1, 2);
        l_i[0] = l_i[0] * corr0 + rs0;  m_i[0] = mn0;
        l_i[1] = l_i[1] * corr1 + rs1;  m_i[1] = mn1;

#pragma unroll
        for (int t = 0; t < 16; t++) {
            oacc[t][0] *= corr0; oacc[t][1] *= corr0;
            oacc[t][2] *= corr1; oacc[t][3] *= corr1;
        }

        // ---- O += P @ V (bf16x3), V via ldmatrix.trans ----
#pragma unroll
        for (int kc = 0; kc < 4; kc++) {
#pragma unroll
            for (int nt2 = 0; nt2 < 8; nt2++) {
                uint32_t bh[4], bl[4];
                ldsm_x4_t(bh[0], bh[1], bh[2], bh[3],
                          smem_u32(&Vh[(kc * 16 + v_row) * FSTR + nt2 * 16 + v_col]));
                ldsm_x4_t(bl[0], bl[1], bl[2], bl[3],
                          smem_u32(&Vl[(kc * 16 + v_row) * FSTR + nt2 * 16 + v_col]));
                mma_bf16(oacc[nt2 * 2], aPh[kc], bh);
                mma_bf16(oacc[nt2 * 2], aPh[kc], bl);
                mma_bf16(oacc[nt2 * 2], aPl[kc], bh);
                mma_bf16(oacc[nt2 * 2 + 1], aPh[kc], bh + 2);
                mma_bf16(oacc[nt2 * 2 + 1], aPh[kc], bl + 2);
                mma_bf16(oacc[nt2 * 2 + 1], aPl[kc], bh + 2);
            }
        }
    }

    // ---- epilogue: normalize, write ctx[s][b][n*128+d] ----
    {
        float inv0 = 1.0f / l_i[0];
        float inv1 = 1.0f / l_i[1];
        int s0 = row0 + warp * 16 + gr;
        float* cp0 = ctx + ((size_t)s0 * BATCH + b) * HID + n * HN;
        float* cp1 = ctx + ((size_t)(s0 + 8) * BATCH + b) * HID + n * HN;
#pragma unroll
        for (int t = 0; t < 16; t++) {
            int col = t * 8 + gc;
            float2 v0, v1;
            v0.x = oacc[t][0] * inv0; v0.y = oacc[t][1] * inv0;
            v1.x = oacc[t][2] * inv1; v1.y = oacc[t][3] * inv1;
            *(float2*)(cp0 + col) = v0;
            *(float2*)(cp1 + col) = v1;
        }
    }
}

// ---------------------------------------------------------------------------
// Launch
// ---------------------------------------------------------------------------
extern "C" void kernel_launch(void* const* d_in, const int* in_sizes, int n_in,
                              void* d_out, int out_size)
{
    const float* hidden  = (const float*)d_in[0];
    // d_in[1] = attention_mask (causal; handled analytically)
    const float* w_qkv   = (const float*)d_in[2];
    const float* b_qkv   = (const float*)d_in[3];
    const float* w_dense = (const float*)d_in[4];
    const float* b_dense = (const float*)d_in[5];
    float* out = (float*)d_out;

    float *qkv, *q, *k, *v, *ctx;
    cudaGetSymbolAddress((void**)&qkv, g_qkv);
    cudaGetSymbolAddress((void**)&q,   g_q);
    cudaGetSymbolAddress((void**)&k,   g_k);
    cudaGetSymbolAddress((void**)&v,   g_v);
    cudaGetSymbolAddress((void**)&ctx, g_ctx);

    cudaFuncSetAttribute(hmma_gemm_nt_bias,
                         cudaFuncAttributeMaxDynamicSharedMemorySize, GEMM_SMEM_BYTES);
    cudaFuncSetAttribute(flash_hmma_kernel,
                         cudaFuncAttributeMaxDynamicSharedMemorySize, FA_SMEM_BYTES);

    // 1) QKV projection (tensor cores)
    hmma_gemm_nt_bias<<<dim3(QKV_N / TBN, M_ROWS / TBM), 256, GEMM_SMEM_BYTES>>>(
        hidden, w_qkv, b_qkv, qkv, M_ROWS, QKV_N, HID);

    // 2) Rotary + split into [b][n][s][d]
    {
        int total = S_LEN * BATCH * NP * (HN / 2);
        rotary_split_kernel<<<total / 256, 256>>>(qkv, q, k, v);
    }

    // 3) Causal flash attention (tensor cores) -> ctx[s][b][h]
    flash_hmma_kernel<<<dim3(S_LEN / FBM, NP, BATCH), 256, FA_SMEM_BYTES>>>(
        q, k, v, ctx);

    // 4) Dense projection (tensor cores)
    hmma_gemm_nt_bias<<<dim3(HID / TBN, M_ROWS / TBM), 256, GEMM_SMEM_BYTES>>>(
        ctx, w_dense, b_dense, out, M_ROWS, HID, HID);
}

// round 6
// speedup vs baseline: 5.5575x; 1.5894x over previous
#include <cuda_runtime.h>
#include <cuda_bf16.h>
#include <math.h>
#include <stdint.h>

// Problem constants
#define S_LEN 2048
#define BATCH 2
#define HID   2048
#define NP    16
#define HN    128
#define M_ROWS (S_LEN*BATCH)     // 4096
#define QKV_N  (3*HID)           // 6144
#define HEAD_ELEMS ((size_t)BATCH * NP * S_LEN * HN)   // 8388608

// ---------------------------------------------------------------------------
// Scratch (device globals; no runtime allocation allowed)
// ---------------------------------------------------------------------------
__device__ float g_qkv[(size_t)M_ROWS * QKV_N];                 // [4096][6144]
__device__ float g_ctx[(size_t)M_ROWS * HID];                   // [s][b][h]
__device__ __nv_bfloat16 g_qh[HEAD_ELEMS], g_ql[HEAD_ELEMS];    // [b][n][s][d]
__device__ __nv_bfloat16 g_kh[HEAD_ELEMS], g_kl[HEAD_ELEMS];
__device__ __nv_bfloat16 g_vh[HEAD_ELEMS], g_vl[HEAD_ELEMS];

// ---------------------------------------------------------------------------
// PTX helpers
// ---------------------------------------------------------------------------
__device__ __forceinline__ uint32_t smem_u32(const void* p) {
    return (uint32_t)__cvta_generic_to_shared(p);
}
__device__ __forceinline__ void ldsm_x4(uint32_t& r0, uint32_t& r1,
                                        uint32_t& r2, uint32_t& r3, uint32_t addr) {
    asm volatile("ldmatrix.sync.aligned.m8n8.x4.shared.b16 {%0,%1,%2,%3}, [%4];"
        : "=r"(r0), "=r"(r1), "=r"(r2), "=r"(r3) : "r"(addr));
}
__device__ __forceinline__ void ldsm_x4_t(uint32_t& r0, uint32_t& r1,
                                          uint32_t& r2, uint32_t& r3, uint32_t addr) {
    asm volatile("ldmatrix.sync.aligned.m8n8.x4.trans.shared.b16 {%0,%1,%2,%3}, [%4];"
        : "=r"(r0), "=r"(r1), "=r"(r2), "=r"(r3) : "r"(addr));
}
__device__ __forceinline__ void mma_bf16(float* d, const uint32_t* a, const uint32_t* b) {
    asm volatile("mma.sync.aligned.m16n8k16.row.col.f32.bf16.bf16.f32 "
        "{%0,%1,%2,%3}, {%4,%5,%6,%7}, {%8,%9}, {%0,%1,%2,%3};"
        : "+f"(d[0]), "+f"(d[1]), "+f"(d[2]), "+f"(d[3])
        : "r"(a[0]), "r"(a[1]), "r"(a[2]), "r"(a[3]), "r"(b[0]), "r"(b[1]));
}
__device__ __forceinline__ uint32_t pack_bf2(float a, float b) {
    __nv_bfloat162 t;
    t.x = __float2bfloat16_rn(a);
    t.y = __float2bfloat16_rn(b);
    return *(uint32_t*)&t;
}
__device__ __forceinline__ void cp16(void* sdst, const void* gsrc) {
    asm volatile("cp.async.cg.shared.global [%0], [%1], 16;\n"
        :: "r"(smem_u32(sdst)), "l"(gsrc));
}
__device__ __forceinline__ void cp_commit() {
    asm volatile("cp.async.commit_group;\n");
}
template <int N>
__device__ __forceinline__ void cp_wait() {
    asm volatile("cp.async.wait_group %0;\n" :: "n"(N));
}

// ---------------------------------------------------------------------------
// HMMA bf16x3 GEMM (NT): C[M,N] = A[M,K] * W[N,K]^T + bias[N]   (unchanged)
// ---------------------------------------------------------------------------
#define TBM 128
#define TBN 128
#define TBK 32
#define TSTR 40
#define GEMM_SMEM_BYTES (2*2*TBM*TSTR*2*2)   // 81920

__global__ __launch_bounds__(256, 1) void hmma_gemm_nt_bias(
    const float* __restrict__ A, const float* __restrict__ W,
    const float* __restrict__ bias, float* __restrict__ C,
    int M, int N, int K)
{
    extern __shared__ __nv_bfloat16 smg[];
    __nv_bfloat16* As = smg;
    __nv_bfloat16* Bs = smg + 2*2*TBM*TSTR;

    const int tid  = threadIdx.x;
    const int bx   = blockIdx.x, by = blockIdx.y;
    const int warp = tid >> 5, lane = tid & 31;
    const int wr   = warp & 3;
    const int wc   = warp >> 2;

    const int lr  = tid >> 3;
    const int lkc = (tid & 7) * 4;

    const float* Ag = A + (size_t)(by * TBM) * K;
    const float* Wg = W + (size_t)(bx * TBN) * K;

    float4 sa[4], sb[4];

    auto load_g = [&](int kt) {
#pragma unroll
        for (int j = 0; j < 4; j++) {
            int r = lr + 32 * j;
            sa[j] = *(const float4*)(Ag + (size_t)r * K + kt * TBK + lkc);
            sb[j] = *(const float4*)(Wg + (size_t)r * K + kt * TBK + lkc);
        }
    };

    auto cvt_store = [&](int s) {
#pragma unroll
        for (int j = 0; j < 4; j++) {
            int r = lr + 32 * j;
#pragma unroll
            for (int mtx = 0; mtx < 2; mtx++) {
                float4 v = mtx ? sb[j] : sa[j];
                __nv_bfloat16* dst = mtx ? Bs : As;
                __nv_bfloat16 h0 = __float2bfloat16_rn(v.x);
                __nv_bfloat16 h1 = __float2bfloat16_rn(v.y);
                __nv_bfloat16 h2 = __float2bfloat16_rn(v.z);
                __nv_bfloat16 h3 = __float2bfloat16_rn(v.w);
                __nv_bfloat16 l0 = __float2bfloat16_rn(v.x - __bfloat162float(h0));
                __nv_bfloat16 l1 = __float2bfloat16_rn(v.y - __bfloat162float(h1));
                __nv_bfloat16 l2 = __float2bfloat16_rn(v.z - __bfloat162float(h2));
                __nv_bfloat16 l3 = __float2bfloat16_rn(v.w - __bfloat162float(h3));
                size_t bh = ((size_t)(s * 2 + 0) * TBM + r) * TSTR + lkc;
                size_t bl = ((size_t)(s * 2 + 1) * TBM + r) * TSTR + lkc;
                __nv_bfloat162 t;
                t.x = h0; t.y = h1; *(__nv_bfloat162*)&dst[bh]     = t;
                t.x = h2; t.y = h3; *(__nv_bfloat162*)&dst[bh + 2] = t;
                t.x = l0; t.y = l1; *(__nv_bfloat162*)&dst[bl]     = t;
                t.x = l2; t.y = l3; *(__nv_bfloat162*)&dst[bl + 2] = t;
            }
        }
    };

    float acc[2][8][4];
#pragma unroll
    for (int mi = 0; mi < 2; mi++)
#pragma unroll
        for (int ni = 0; ni < 8; ni++)
#pragma unroll
            for (int e = 0; e < 4; e++) acc[mi][ni][e] = 0.f;

    const int a_row = wr * 32 + (lane & 15);
    const int a_kh  = (lane >> 4) * 8;
    const int bg    = lane >> 3;
    const int b_row = wc * 64 + ((bg >> 1) << 3) + (lane & 7);
    const int b_kh  = (bg & 1) * 8;

    auto compute = [&](int s) {
#pragma unroll
        for (int kk = 0; kk < TBK; kk += 16) {
            uint32_t af[2][2][4];
#pragma unroll
            for (int p = 0; p < 2; p++)
#pragma unroll
                for (int mi = 0; mi < 2; mi++) {
                    const __nv_bfloat16* ptr =
                        &As[((size_t)(s * 2 + p) * TBM + a_row + mi * 16) * TSTR + kk + a_kh];
                    ldsm_x4(af[p][mi][0], af[p][mi][1], af[p][mi][2], af[p][mi][3],
                            smem_u32(ptr));
                }
            uint32_t bf[2][8][2];
#pragma unroll
            for (int p = 0; p < 2; p++)
#pragma unroll
                for (int np = 0; np < 4; np++) {
                    const __nv_bfloat16* ptr =
                        &Bs[((size_t)(s * 2 + p) * TBN + b_row + np * 16) * TSTR + kk + b_kh];
                    uint32_t r0, r1, r2, r3;
                    ldsm_x4(r0, r1, r2, r3, smem_u32(ptr));
                    bf[p][np * 2][0] = r0;     bf[p][np * 2][1] = r1;
                    bf[p][np * 2 + 1][0] = r2; bf[p][np * 2 + 1][1] = r3;
                }
#pragma unroll
            for (int mi = 0; mi < 2; mi++)
#pragma unroll
                for (int ni = 0; ni < 8; ni++) {
                    mma_bf16(acc[mi][ni], af[0][mi], bf[0][ni]);
                    mma_bf16(acc[mi][ni], af[0][mi], bf[1][ni]);
                    mma_bf16(acc[mi][ni], af[1][mi], bf[0][ni]);
                }
        }
    };

    const int ntiles = K / TBK;
    load_g(0);
    cvt_store(0);
    __syncthreads();
#pragma unroll 1
    for (int kt = 0; kt < ntiles; kt++) {
        if (kt + 1 < ntiles) load_g(kt + 1);
        compute(kt & 1);
        if (kt + 1 < ntiles) {
            cvt_store((kt + 1) & 1);
            __syncthreads();
        }
    }

    const int gr = lane >> 2, gc = (lane & 3) * 2;
#pragma unroll
    for (int mi = 0; mi < 2; mi++) {
        int row = by * TBM + wr * 32 + mi * 16 + gr;
#pragma unroll
        for (int ni = 0; ni < 8; ni++) {
            int col = bx * TBN + wc * 64 + ni * 8 + gc;
            float b0 = bias[col], b1 = bias[col + 1];
            float2 v0, v1;
            v0.x = acc[mi][ni][0] + b0; v0.y = acc[mi][ni][1] + b1;
            v1.x = acc[mi][ni][2] + b0; v1.y = acc[mi][ni][3] + b1;
            *(float2*)&C[(size_t)row * N + col] = v0;
            *(float2*)&C[(size_t)(row + 8) * N + col] = v1;
        }
    }
}

// ---------------------------------------------------------------------------
// Rotary + QKV split/transpose + bf16 hi/lo split.
// mixed[s][b][n][384] -> Qh/Ql/Kh/Kl/Vh/Vl [b][n][s][128] (Q pre-scaled).
// ---------------------------------------------------------------------------
__global__ __launch_bounds__(256) void rotary_split_kernel(
    const float* __restrict__ mixed,
    __nv_bfloat16* __restrict__ Qh, __nv_bfloat16* __restrict__ Ql,
    __nv_bfloat16* __restrict__ Kh, __nv_bfloat16* __restrict__ Kl,
    __nv_bfloat16* __restrict__ Vh, __nv_bfloat16* __restrict__ Vl)
{
    int idx = blockIdx.x * blockDim.x + threadIdx.x;
    int i = idx & 63;
    int rest = idx >> 6;
    int n = rest & (NP - 1); rest >>= 4;
    int b = rest & (BATCH - 1);
    int s = rest >> 1;

    const float* src = mixed + (((size_t)(s * BATCH + b)) * NP + n) * (3 * HN);
    size_t dst = (((size_t)b * NP + n) * S_LEN + s) * HN;

    float expo = (float)(2 * i) / (float)HN;
    float freq = powf(1e-4f, expo);
    float ang  = (float)s * freq;
    float sn, cs;
    sincosf(ang, &sn, &cs);

    const float qscale = 0.0883883476483184f;     // 1/sqrt(128)

    float ql_ = src[i],       qr_ = src[i + 64];
    float kl_ = src[128 + i], kr_ = src[192 + i];

    float q0 = (cs * ql_ - sn * qr_) * qscale;
    float q1 = (sn * ql_ + cs * qr_) * qscale;
    float k0 = cs * kl_ - sn * kr_;
    float k1 = sn * kl_ + cs * kr_;
    float v0 = src[256 + i];
    float v1 = src[320 + i];

    __nv_bfloat16 h;
    h = __float2bfloat16_rn(q0); Qh[dst + i] = h;
    Ql[dst + i] = __float2bfloat16_rn(q0 - __bfloat162float(h));
    h = __float2bfloat16_rn(q1); Qh[dst + 64 + i] = h;
    Ql[dst + 64 + i] = __float2bfloat16_rn(q1 - __bfloat162float(h));
    h = __float2bfloat16_rn(k0); Kh[dst + i] = h;
    Kl[dst + i] = __float2bfloat16_rn(k0 - __bfloat162float(h));
    h = __float2bfloat16_rn(k1); Kh[dst + 64 + i] = h;
    Kl[dst + 64 + i] = __float2bfloat16_rn(k1 - __bfloat162float(h));
    h = __float2bfloat16_rn(v0); Vh[dst + i] = h;
    Vl[dst + i] = __float2bfloat16_rn(v0 - __bfloat162float(h));
    h = __float2bfloat16_rn(v1); Vh[dst + 64 + i] = h;
    Vl[dst + 64 + i] = __float2bfloat16_rn(v1 - __bfloat162float(h));
}

// ---------------------------------------------------------------------------
// HMMA flash attention (bf16x3, FA2-style), pre-split inputs, cp.async
// double-buffered K/V tiles.  Grid (16, NP, B), 256 threads = 8 warps.
// ---------------------------------------------------------------------------
#define FBM 128
#define FBN 64
#define FSTR 136
#define FA_STAGE_ELEMS (4*FBN*FSTR)
#define FA_SMEM_BYTES ((2*FBM*FSTR + 2*FA_STAGE_ELEMS) * 2)   // 208896

__global__ __launch_bounds__(256, 1) void flash_hmma_kernel(
    const __nv_bfloat16* __restrict__ Qhg, const __nv_bfloat16* __restrict__ Qlg,
    const __nv_bfloat16* __restrict__ Khg, const __nv_bfloat16* __restrict__ Klg,
    const __nv_bfloat16* __restrict__ Vhg, const __nv_bfloat16* __restrict__ Vlg,
    float* __restrict__ ctx)
{
    extern __shared__ __nv_bfloat16 fsm[];
    __nv_bfloat16* Qh = fsm;
    __nv_bfloat16* Ql = Qh + FBM * FSTR;
    __nv_bfloat16* St = Ql + FBM * FSTR;   // two stages of [Kh|Kl|Vh|Vl]

    const int qt = gridDim.x - 1 - blockIdx.x;    // heavy tiles first
    const int n  = blockIdx.y;
    const int b  = blockIdx.z;
    const int tid  = threadIdx.x;
    const int warp = tid >> 5, lane = tid & 31;

    const size_t head = ((size_t)b * NP + n) * (size_t)S_LEN * HN;
    const int row0 = qt * FBM;

    auto prefetch = [&](int kt, int s) {
        __nv_bfloat16* Khs = St + (size_t)s * FA_STAGE_ELEMS;
        __nv_bfloat16* Kls = Khs + FBN * FSTR;
        __nv_bfloat16* Vhs = Kls + FBN * FSTR;
        __nv_bfloat16* Vls = Vhs + FBN * FSTR;
        size_t base = head + (size_t)(kt * FBN) * HN;
#pragma unroll
        for (int j = 0; j < 4; j++) {
            int lin = tid + j * 256;           // 1024 chunks of 8 bf16
            int r = lin >> 4, c = (lin & 15) * 8;
            size_t g = base + (size_t)r * HN + c;
            int so = r * FSTR + c;
            cp16(&Khs[so], Khg + g);
            cp16(&Kls[so], Klg + g);
            cp16(&Vhs[so], Vhg + g);
            cp16(&Vls[so], Vlg + g);
        }
    };

    // ---- prologue: Q tile + first K/V tile, one cp.async group ----
#pragma unroll
    for (int j = 0; j < 8; j++) {
        int lin = tid + j * 256;               // 2048 chunks
        int r = lin >> 4, c = (lin & 15) * 8;
        size_t g = head + (size_t)(row0 + r) * HN + c;
        cp16(&Qh[r * FSTR + c], Qhg + g);
        cp16(&Ql[r * FSTR + c], Qlg + g);
    }
    prefetch(0, 0);
    cp_commit();

    // accumulators
    float oacc[16][4];
#pragma unroll
    for (int t = 0; t < 16; t++)
#pragma unroll
        for (int e = 0; e < 4; e++) oacc[t][e] = 0.f;
    float m_i[2] = {-1e30f, -1e30f};
    float l_i[2] = {0.f, 0.f};

    // fragment lane addressing
    const int a_row = warp * 16 + (lane & 15);
    const int a_kh  = (lane >> 4) * 8;
    const int b_r   = (lane >> 4) * 8 + (lane & 7);       // K (non-trans)
    const int b_kh  = ((lane >> 3) & 1) * 8;
    const int v_row = ((lane >> 3) & 1) * 8 + (lane & 7); // V (trans)
    const int v_col = (lane >> 4) * 8;
    const int gr    = lane >> 2;
    const int gc    = (lane & 3) * 2;
    const int wrow_last = row0 + warp * 16 + 15;

    const int nkt = (row0 + FBM) / FBN;
#pragma unroll 1
    for (int kt = 0; kt < nkt; kt++) {
        const int kr0 = kt * FBN;
        const int s = kt & 1;

        if (kt + 1 < nkt) {
            prefetch(kt + 1, (kt + 1) & 1);
            cp_commit();
            cp_wait<1>();
        } else {
            cp_wait<0>();
        }
        __syncthreads();   // tile kt visible to all

        if (kr0 <= wrow_last) {   // not fully masked for this warp
            __nv_bfloat16* Khs = St + (size_t)s * FA_STAGE_ELEMS;
            __nv_bfloat16* Kls = Khs + FBN * FSTR;
            __nv_bfloat16* Vhs = Kls + FBN * FSTR;
            __nv_bfloat16* Vls = Vhs + FBN * FSTR;

            // ---- S = Q K^T (bf16x3) ----
            float sacc[8][4];
#pragma unroll
            for (int t = 0; t < 8; t++)
#pragma unroll
                for (int e = 0; e < 4; e++) sacc[t][e] = 0.f;

#pragma unroll
            for (int kk = 0; kk < 8; kk++) {
                uint32_t aH[4], aL[4];
                ldsm_x4(aH[0], aH[1], aH[2], aH[3],
                        smem_u32(&Qh[a_row * FSTR + kk * 16 + a_kh]));
                ldsm_x4(aL[0], aL[1], aL[2], aL[3],
                        smem_u32(&Ql[a_row * FSTR + kk * 16 + a_kh]));
#pragma unroll
                for (int nt2 = 0; nt2 < 4; nt2++) {
                    uint32_t bh[4], bl[4];
                    ldsm_x4(bh[0], bh[1], bh[2], bh[3],
                            smem_u32(&Khs[(nt2 * 16 + b_r) * FSTR + kk * 16 + b_kh]));
                    ldsm_x4(bl[0], bl[1], bl[2], bl[3],
                            smem_u32(&Kls[(nt2 * 16 + b_r) * FSTR + kk * 16 + b_kh]));
                    mma_bf16(sacc[nt2 * 2], aH, bh);
                    mma_bf16(sacc[nt2 * 2], aH, bl);
                    mma_bf16(sacc[nt2 * 2], aL, bh);
                    mma_bf16(sacc[nt2 * 2 + 1], aH, bh + 2);
                    mma_bf16(sacc[nt2 * 2 + 1], aH, bl + 2);
                    mma_bf16(sacc[nt2 * 2 + 1], aL, bh + 2);
                }
            }

            // ---- causal mask ----
            if (kr0 + FBN - 1 > row0 + warp * 16) {
                int grow0 = row0 + warp * 16 + gr;
#pragma unroll
                for (int t = 0; t < 8; t++) {
                    int colb = kr0 + t * 8 + gc;
                    if (colb     > grow0)     sacc[t][0] = -1e30f;
                    if (colb + 1 > grow0)     sacc[t][1] = -1e30f;
                    if (colb     > grow0 + 8) sacc[t][2] = -1e30f;
                    if (colb + 1 > grow0 + 8) sacc[t][3] = -1e30f;
                }
            }

            // ---- online softmax ----
            float mx0 = -1e30f, mx1 = -1e30f;
#pragma unroll
            for (int t = 0; t < 8; t++) {
                mx0 = fmaxf(mx0, fmaxf(sacc[t][0], sacc[t][1]));
                mx1 = fmaxf(mx1, fmaxf(sacc[t][2], sacc[t][3]));
            }
            mx0 = fmaxf(mx0, __shfl_xor_sync(0xffffffffu, mx0, 1));
            mx0 = fmaxf(mx0, __shfl_xor_sync(0xffffffffu, mx0, 2));
            mx1 = fmaxf(mx1, __shfl_xor_sync(0xffffffffu, mx1, 1));
            mx1 = fmaxf(mx1, __shfl_xor_sync(0xffffffffu, mx1, 2));
            float mn0 = fmaxf(m_i[0], mx0);
            float mn1 = fmaxf(m_i[1], mx1);
            float corr0 = __expf(m_i[0] - mn0);
            float corr1 = __expf(m_i[1] - mn1);

            uint32_t aPh[4][4], aPl[4][4];
            float rs0 = 0.f, rs1 = 0.f;
#pragma unroll
            for (int t = 0; t < 8; t++) {
                float p00 = __expf(sacc[t][0] - mn0);
                float p01 = __expf(sacc[t][1] - mn0);
                float p10 = __expf(sacc[t][2] - mn1);
                float p11 = __expf(sacc[t][3] - mn1);
                rs0 += p00 + p01;
                rs1 += p10 + p11;
                int kc = t >> 1, half = (t & 1) * 2;
                float h00 = __bfloat162float(__float2bfloat16_rn(p00));
                float h01 = __bfloat162float(__float2bfloat16_rn(p01));
                float h10 = __bfloat162float(__float2bfloat16_rn(p10));
                float h11 = __bfloat162float(__float2bfloat16_rn(p11));
                aPh[kc][half]     = pack_bf2(h00, h01);
                aPh[kc][half + 1] = pack_bf2(h10, h11);
                aPl[kc][half]     = pack_bf2(p00 - h00, p01 - h01);
                aPl[kc][half + 1] = pack_bf2(p10 - h10, p11 - h11);
            }
            rs0 += __shfl_xor_sync(0xffffffffu, rs0, 1);
            rs0 += __shfl_xor_sync(0xffffffffu, rs0, 2);
            rs1 += __shfl_xor_sync(0xffffffffu, rs1, 1);
            rs1 += __shfl_xor_sync(0xffffffffu, rs1, 2);
            l_i[0] = l_i[0] * corr0 + rs0;  m_i[0] = mn0;
            l_i[1] = l_i[1] * corr1 + rs1;  m_i[1] = mn1;

#pragma unroll
            for (int t = 0; t < 16; t++) {
                oacc[t][0] *= corr0; oacc[t][1] *= corr0;
                oacc[t][2] *= corr1; oacc[t][3] *= corr1;
            }

            // ---- O += P @ V (bf16x3), V via ldmatrix.trans ----
#pragma unroll
            for (int kc = 0; kc < 4; kc++) {
#pragma unroll
                for (int nt2 = 0; nt2 < 8; nt2++) {
                    uint32_t bh[4], bl[4];
                    ldsm_x4_t(bh[0], bh[1], bh[2], bh[3],
                              smem_u32(&Vhs[(kc * 16 + v_row) * FSTR + nt2 * 16 + v_col]));
                    ldsm_x4_t(bl[0], bl[1], bl[2], bl[3],
                              smem_u32(&Vls[(kc * 16 + v_row) * FSTR + nt2 * 16 + v_col]));
                    mma_bf16(oacc[nt2 * 2], aPh[kc], bh);
                    mma_bf16(oacc[nt2 * 2], aPh[kc], bl);
                    mma_bf16(oacc[nt2 * 2], aPl[kc], bh);
                    mma_bf16(oacc[nt2 * 2 + 1], aPh[kc], bh + 2);
                    mma_bf16(oacc[nt2 * 2 + 1], aPh[kc], bl + 2);
                    mma_bf16(oacc[nt2 * 2 + 1], aPl[kc], bh + 2);
                }
            }
        }

        __syncthreads();   // everyone done reading stage s before next prefetch
    }

    // ---- epilogue: normalize, write ctx[s][b][n*128+d] ----
    {
        float inv0 = 1.0f / l_i[0];
        float inv1 = 1.0f / l_i[1];
        int s0 = row0 + warp * 16 + gr;
        float* cp0 = ctx + ((size_t)s0 * BATCH + b) * HID + n * HN;
        float* cp1 = ctx + ((size_t)(s0 + 8) * BATCH + b) * HID + n * HN;
#pragma unroll
        for (int t = 0; t < 16; t++) {
            int col = t * 8 + gc;
            float2 v0, v1;
            v0.x = oacc[t][0] * inv0; v0.y = oacc[t][1] * inv0;
            v1.x = oacc[t][2] * inv1; v1.y = oacc[t][3] * inv1;
            *(float2*)(cp0 + col) = v0;
            *(float2*)(cp1 + col) = v1;
        }
    }
}

// ---------------------------------------------------------------------------
// Launch
// ---------------------------------------------------------------------------
extern "C" void kernel_launch(void* const* d_in, const int* in_sizes, int n_in,
                              void* d_out, int out_size)
{
    const float* hidden  = (const float*)d_in[0];
    // d_in[1] = attention_mask (causal; handled analytically)
    const float* w_qkv   = (const float*)d_in[2];
    const float* b_qkv   = (const float*)d_in[3];
    const float* w_dense = (const float*)d_in[4];
    const float* b_dense = (const float*)d_in[5];
    float* out = (float*)d_out;

    float *qkv, *ctx;
    __nv_bfloat16 *qh, *ql, *kh, *kl, *vh, *vl;
    cudaGetSymbolAddress((void**)&qkv, g_qkv);
    cudaGetSymbolAddress((void**)&ctx, g_ctx);
    cudaGetSymbolAddress((void**)&qh,  g_qh);
    cudaGetSymbolAddress((void**)&ql,  g_ql);
    cudaGetSymbolAddress((void**)&kh,  g_kh);
    cudaGetSymbolAddress((void**)&kl,  g_kl);
    cudaGetSymbolAddress((void**)&vh,  g_vh);
    cudaGetSymbolAddress((void**)&vl,  g_vl);

    cudaFuncSetAttribute(hmma_gemm_nt_bias,
                         cudaFuncAttributeMaxDynamicSharedMemorySize, GEMM_SMEM_BYTES);
    cudaFuncSetAttribute(flash_hmma_kernel,
                         cudaFuncAttributeMaxDynamicSharedMemorySize, FA_SMEM_BYTES);

    // 1) QKV projection (tensor cores)
    hmma_gemm_nt_bias<<<dim3(QKV_N / TBN, M_ROWS / TBM), 256, GEMM_SMEM_BYTES>>>(
        hidden, w_qkv, b_qkv, qkv, M_ROWS, QKV_N, HID);

    // 2) Rotary + split into bf16 hi/lo planes [b][n][s][d]
    {
        int total = S_LEN * BATCH * NP * (HN / 2);
        rotary_split_kernel<<<total / 256, 256>>>(qkv, qh, ql, kh, kl, vh, vl);
    }

    // 3) Causal flash attention (tensor cores) -> ctx[s][b][h]
    flash_hmma_kernel<<<dim3(S_LEN / FBM, NP, BATCH), 256, FA_SMEM_BYTES>>>(
        qh, ql, kh, kl, vh, vl, ctx);

    // 4) Dense projection (tensor cores)
    hmma_gemm_nt_bias<<<dim3(HID / TBN, M_ROWS / TBM), 256, GEMM_SMEM_BYTES>>>(
        ctx, w_dense, b_dense, out, M_ROWS, HID, HID);
}